// round 1
// baseline (speedup 1.0000x reference)
#include <cuda_runtime.h>
#include <cuda_bf16.h>
#include <cstdint>

#define BB 256   // batch
#define TT 512   // encoder steps
#define FF 64    // input features
#define HH 1024  // hidden
#define TLEN 64  // decoder steps
#define N3 3072  // 3*H output columns (gate-interleaved)
#define KK 3072  // augmented K: [h_hi | h_lo | h_hi]
#define NC 48    // K chunks of 64

// ---------------- device scratch (static globals; no allocation) ----------------
__device__ __nv_bfloat16 g_Waug_enc[(size_t)N3 * KK];   // 18.9 MB
__device__ __nv_bfloat16 g_Waug_dec[(size_t)N3 * KK];   // 18.9 MB
__device__ __nv_bfloat16 g_haug[2][(size_t)BB * KK];    // double-buffered h operand
__device__ float g_bih_e[N3], g_bhh_e[N3], g_bih_d[N3], g_bhh_d[N3]; // permuted biases
__device__ float g_Wihp_e[(size_t)HH * 192];            // enc W_ih, per-unit [r(64)|z(64)|n(64)]
__device__ float g_Wih_d[N3];                           // dec W_ih (scalar input), permuted

// ---------------- small PTX helpers ----------------
__device__ __forceinline__ void cp16(uint32_t smaddr, const void* g) {
    asm volatile("cp.async.cg.shared.global [%0], [%1], 16;" :: "r"(smaddr), "l"(g));
}
__device__ __forceinline__ void ldsm_x4(uint32_t* r, uint32_t addr) {
    asm volatile("ldmatrix.sync.aligned.m8n8.x4.shared.b16 {%0,%1,%2,%3}, [%4];"
                 : "=r"(r[0]), "=r"(r[1]), "=r"(r[2]), "=r"(r[3]) : "r"(addr));
}
__device__ __forceinline__ void ldsm_x2(uint32_t* r, uint32_t addr) {
    asm volatile("ldmatrix.sync.aligned.m8n8.x2.shared.b16 {%0,%1}, [%2];"
                 : "=r"(r[0]), "=r"(r[1]) : "r"(addr));
}
__device__ __forceinline__ void mma_bf16(float* c, const uint32_t* a, const uint32_t* b) {
    asm volatile("mma.sync.aligned.m16n8k16.row.col.f32.bf16.bf16.f32 "
                 "{%0,%1,%2,%3}, {%4,%5,%6,%7}, {%8,%9}, {%0,%1,%2,%3};"
                 : "+f"(c[0]), "+f"(c[1]), "+f"(c[2]), "+f"(c[3])
                 : "r"(a[0]), "r"(a[1]), "r"(a[2]), "r"(a[3]), "r"(b[0]), "r"(b[1]));
}

// ---------------- prep: build augmented, gate-interleaved bf16x2-split weights ----------------
// Permuted row j = 3u+g  <->  original row g*H+u.
// Augmented cols: k in [0,1024): W_hi[k]; [1024,2048): W_hi[k-1024]; [2048,3072): W_lo[k-2048]
__global__ void prep_weights(const float* __restrict__ encW, const float* __restrict__ decW) {
    size_t idx = (size_t)blockIdx.x * blockDim.x + threadIdx.x;
    const size_t one = (size_t)N3 * KK;
    if (idx >= 2 * one) return;
    int which = idx >= one;
    size_t rem = which ? idx - one : idx;
    int j = (int)(rem / KK);
    int k = (int)(rem % KK);
    int u = j / 3, g = j - 3 * u;
    int korig = k & 1023;
    int region = k >> 10;
    const float* W = which ? decW : encW;
    float w = W[(size_t)(g * HH + u) * HH + korig];
    __nv_bfloat16 hi = __float2bfloat16(w);
    __nv_bfloat16 out = (region < 2) ? hi : __float2bfloat16(w - __bfloat162float(hi));
    (which ? g_Waug_dec : g_Waug_enc)[(size_t)j * KK + k] = out;
}

// ---------------- prep: biases, permuted W_ih, zero h, init d_out = fc_b ----------------
__global__ void prep_misc(const float* __restrict__ ebih, const float* __restrict__ ebhh,
                          const float* __restrict__ dbih, const float* __restrict__ dbhh,
                          const float* __restrict__ eWih, const float* __restrict__ dWih,
                          const float* __restrict__ fcb, float* __restrict__ dout) {
    int tid = blockIdx.x * blockDim.x + threadIdx.x;
    int stride = gridDim.x * blockDim.x;
    for (int i = tid; i < N3; i += stride) {
        int u = i / 3, g = i - 3 * u;
        int o = g * HH + u;
        g_bih_e[i] = ebih[o];
        g_bhh_e[i] = ebhh[o];
        g_bih_d[i] = dbih[o];
        g_bhh_d[i] = dbhh[o];
        g_Wih_d[i] = dWih[o];    // dec_W_ih is [3H,1]
    }
    for (int i = tid; i < HH * 192; i += stride) {
        int u = i / 192, rem = i - u * 192;
        int g = rem >> 6, f = rem & 63;
        g_Wihp_e[i] = eWih[(size_t)(g * HH + u) * FF + f];
    }
    for (int i = tid; i < 2 * BB * KK / 2; i += stride) {   // zero both h buffers (as u32)
        ((uint32_t*)g_haug)[i] = 0u;
    }
    for (int i = tid; i < BB * TLEN; i += stride) dout[i] = fcb[0];
}

// ---------------- one recurrent step: GEMM (bf16x3) + fused GRU epilogue ----------------
// grid (32, 4): blockIdx.x = 96-col tile over N3, blockIdx.y = 64-row tile over batch.
// mode 0 = encoder (t indexes x), mode 1 = decoder (t = s; input is dout[:, s-1])
__global__ __launch_bounds__(256) void gru_step_kernel(
    int t, int mode, int par,
    const float* __restrict__ x, const float* __restrict__ fcW, float* __restrict__ dout)
{
    const __nv_bfloat16* __restrict__ Waug = mode ? g_Waug_dec : g_Waug_enc;
    const __nv_bfloat16* __restrict__ hsrc = g_haug[par];
    __nv_bfloat16* __restrict__ hdst = g_haug[par ^ 1];
    const float* __restrict__ bih = mode ? g_bih_d : g_bih_e;
    const float* __restrict__ bhh = mode ? g_bhh_d : g_bhh_e;

    __shared__ __align__(16) unsigned char smem_raw[46080];
    const int tid = threadIdx.x;
    const int lane = tid & 31, warp = tid >> 5;
    const int wm = warp >> 2, wn = warp & 3;     // 2 x 4 warps -> 32x24 warp tiles
    const int nb = blockIdx.x, mb = blockIdx.y;

    uint32_t smA = (uint32_t)__cvta_generic_to_shared(smem_raw);
    uint32_t smB = smA + 2 * 9216;               // A stages: 2 x 64x72 bf16; B: 2 x 96x72

    const __nv_bfloat16* Ag = hsrc + (size_t)(mb * 64) * KK;
    const __nv_bfloat16* Bg = Waug + (size_t)(nb * 96) * KK;

    // ---- prologue load chunk 0 ----
    {
        #pragma unroll
        for (int q = 0; q < 2; q++) {
            int idx = tid + q * 256; int r = idx >> 3, s = idx & 7;
            cp16(smA + r * 144 + s * 16, Ag + (size_t)r * KK + s * 8);
        }
        #pragma unroll
        for (int q = 0; q < 3; q++) {
            int idx = tid + q * 256; int r = idx >> 3, s = idx & 7;
            cp16(smB + r * 144 + s * 16, Bg + (size_t)r * KK + s * 8);
        }
        asm volatile("cp.async.commit_group;" ::: "memory");
    }

    float acc[2][3][4];
    #pragma unroll
    for (int mi = 0; mi < 2; mi++)
        #pragma unroll
        for (int ni = 0; ni < 3; ni++)
            #pragma unroll
            for (int q = 0; q < 4; q++) acc[mi][ni][q] = 0.f;

    // ---- main K loop, double-buffered ----
    for (int c = 0; c < NC; c++) {
        asm volatile("cp.async.wait_group 0;" ::: "memory");
        __syncthreads();
        if (c + 1 < NC) {
            int stg = (c + 1) & 1;
            int k0 = (c + 1) * 64;
            #pragma unroll
            for (int q = 0; q < 2; q++) {
                int idx = tid + q * 256; int r = idx >> 3, s = idx & 7;
                cp16(smA + stg * 9216 + r * 144 + s * 16, Ag + (size_t)r * KK + k0 + s * 8);
            }
            #pragma unroll
            for (int q = 0; q < 3; q++) {
                int idx = tid + q * 256; int r = idx >> 3, s = idx & 7;
                cp16(smB + stg * 13824 + r * 144 + s * 16, Bg + (size_t)r * KK + k0 + s * 8);
            }
            asm volatile("cp.async.commit_group;" ::: "memory");
        }
        const int stg = c & 1;
        #pragma unroll
        for (int ks = 0; ks < 4; ks++) {
            uint32_t ra[2][4], rb[3][2];
            #pragma unroll
            for (int mi = 0; mi < 2; mi++) {
                int row = wm * 32 + mi * 16 + (lane & 15);
                int col = ks * 16 + (lane >> 4) * 8;
                ldsm_x4(ra[mi], smA + stg * 9216 + row * 144 + col * 2);
            }
            #pragma unroll
            for (int ni = 0; ni < 3; ni++) {
                int row = wn * 24 + ni * 8 + (lane & 7);
                int col = ks * 16 + ((lane >> 3) & 1) * 8;
                ldsm_x2(rb[ni], smB + stg * 13824 + row * 144 + col * 2);
            }
            #pragma unroll
            for (int mi = 0; mi < 2; mi++)
                #pragma unroll
                for (int ni = 0; ni < 3; ni++)
                    mma_bf16(acc[mi][ni], ra[mi], rb[ni]);
        }
    }

    // ---- stage accumulators to smem (reuse the operand buffers) ----
    __syncthreads();
    float* Csm = (float*)smem_raw;               // 64 x 96, pitch 99 floats (25344 B)
    float* Xs  = (float*)(smem_raw + 25600);     // 64 x 64 floats for x tile (16384 B)
    #pragma unroll
    for (int mi = 0; mi < 2; mi++)
        #pragma unroll
        for (int ni = 0; ni < 3; ni++) {
            int m = wm * 32 + mi * 16 + (lane >> 2);
            int n = wn * 24 + ni * 8 + ((lane & 3) << 1);
            Csm[m * 99 + n]           = acc[mi][ni][0];
            Csm[m * 99 + n + 1]       = acc[mi][ni][1];
            Csm[(m + 8) * 99 + n]     = acc[mi][ni][2];
            Csm[(m + 8) * 99 + n + 1] = acc[mi][ni][3];
        }
    if (mode == 0) {
        // cooperative load of this tile's x rows: 64 rows x 16 float4
        #pragma unroll
        for (int q = 0; q < 4; q++) {
            int id = tid + q * 256;
            int r = id >> 4, c4 = id & 15;
            ((float4*)Xs)[r * 16 + c4] =
                *(const float4*)(x + ((size_t)(mb * 64 + r) * TT + t) * FF + c4 * 4);
        }
    }
    __syncthreads();

    // ---- fused GRU epilogue: each thread owns (batch bl, 8 hidden units) ----
    const int bl = tid >> 2, uq = tid & 3;
    const int b = mb * 64 + bl;
    float inp = 0.f;
    if (mode && t > 0) inp = dout[b * TLEN + (t - 1)];
    float fcsum = 0.f;
    const float4* xs4 = (const float4*)(Xs + bl * 64);

    #pragma unroll
    for (int i = 0; i < 8; i++) {
        int ul = uq * 8 + i;
        int u = nb * 32 + ul;
        float ar = Csm[bl * 99 + ul * 3 + 0];
        float az = Csm[bl * 99 + ul * 3 + 1];
        float an = Csm[bl * 99 + ul * 3 + 2];
        float gr, gz, gn;
        if (mode == 0) {
            gr = gz = gn = 0.f;
            const float4* wr4 = (const float4*)(g_Wihp_e + (size_t)u * 192);
            #pragma unroll
            for (int q = 0; q < 16; q++) {
                float4 xv = xs4[q];
                float4 a = wr4[q], bq = wr4[16 + q], cq = wr4[32 + q];
                gr += xv.x * a.x + xv.y * a.y + xv.z * a.z + xv.w * a.w;
                gz += xv.x * bq.x + xv.y * bq.y + xv.z * bq.z + xv.w * bq.w;
                gn += xv.x * cq.x + xv.y * cq.y + xv.z * cq.z + xv.w * cq.w;
            }
        } else {
            gr = inp * g_Wih_d[u * 3 + 0];
            gz = inp * g_Wih_d[u * 3 + 1];
            gn = inp * g_Wih_d[u * 3 + 2];
        }
        float hprev = __bfloat162float(hsrc[(size_t)b * KK + u]) +
                      __bfloat162float(hsrc[(size_t)b * KK + 1024 + u]);
        float rg = 1.f / (1.f + __expf(-(gr + bih[u * 3 + 0] + ar + bhh[u * 3 + 0])));
        float zg = 1.f / (1.f + __expf(-(gz + bih[u * 3 + 1] + az + bhh[u * 3 + 1])));
        float ng = tanhf(gn + bih[u * 3 + 2] + rg * (an + bhh[u * 3 + 2]));
        float hn = (1.f - zg) * ng + zg * hprev;
        __nv_bfloat16 hi = __float2bfloat16(hn);
        hdst[(size_t)b * KK + u]        = hi;
        hdst[(size_t)b * KK + 2048 + u] = hi;
        hdst[(size_t)b * KK + 1024 + u] = __float2bfloat16(hn - __bfloat162float(hi));
        if (mode) fcsum += hn * fcW[u];
    }
    if (mode) {
        fcsum += __shfl_down_sync(0xffffffffu, fcsum, 2, 4);
        fcsum += __shfl_down_sync(0xffffffffu, fcsum, 1, 4);
        if (uq == 0) atomicAdd(&dout[b * TLEN + t], fcsum);
    }
}

// ---------------- host launch ----------------
extern "C" void kernel_launch(void* const* d_in, const int* in_sizes, int n_in,
                              void* d_out, int out_size) {
    const float* x    = (const float*)d_in[0];
    const float* eWih = (const float*)d_in[1];
    const float* eWhh = (const float*)d_in[2];
    const float* ebih = (const float*)d_in[3];
    const float* ebhh = (const float*)d_in[4];
    const float* dWih = (const float*)d_in[5];
    const float* dWhh = (const float*)d_in[6];
    const float* dbih = (const float*)d_in[7];
    const float* dbhh = (const float*)d_in[8];
    const float* fcW  = (const float*)d_in[9];
    const float* fcb  = (const float*)d_in[10];
    float* out = (float*)d_out;

    prep_weights<<<(2 * (size_t)N3 * KK + 255) / 256, 256>>>(eWhh, dWhh);
    prep_misc<<<1024, 256>>>(ebih, ebhh, dbih, dbhh, eWih, dWih, fcb, out);

    dim3 grid(N3 / 96, BB / 64);   // (32, 4)
    for (int t = 0; t < TT; t++)
        gru_step_kernel<<<grid, 256>>>(t, 0, t & 1, x, fcW, out);
    for (int s = 0; s < TLEN; s++)
        gru_step_kernel<<<grid, 256>>>(s, 1, s & 1, x, fcW, out);
}

// round 2
// speedup vs baseline: 1.5677x; 1.5677x over previous
#include <cuda_runtime.h>
#include <cuda_bf16.h>
#include <cstdint>

#define BB 256   // batch
#define TT 512   // encoder steps
#define FF 64    // input features
#define HH 1024  // hidden
#define TLEN 64  // decoder steps
#define N3 3072  // 3*H output columns (gate-interleaved)
#define KK 3072  // augmented K: [h_hi | h_lo | h_hi]
#define NC 48    // K chunks of 64
#define NSTG 4   // pipeline stages

// smem geometry: row pitch 72 bf16 (144B) to de-conflict ldmatrix
#define A_STAGE_BYTES (64 * 144)            // 9216
#define B_STAGE_BYTES (96 * 144)            // 13824
#define STAGE_BYTES   (A_STAGE_BYTES + B_STAGE_BYTES)   // 23040
#define SMEM_TOTAL    (NSTG * STAGE_BYTES)  // 92160

// ---------------- device scratch (static globals; no allocation) ----------------
__device__ __nv_bfloat16 g_Waug_enc[(size_t)N3 * KK];   // 18.9 MB
__device__ __nv_bfloat16 g_Waug_dec[(size_t)N3 * KK];   // 18.9 MB
__device__ __nv_bfloat16 g_haug[2][(size_t)BB * KK];    // double-buffered h operand
__device__ float g_bih_e[N3], g_bhh_e[N3], g_bih_d[N3], g_bhh_d[N3]; // permuted biases
__device__ float g_Wihp_e[(size_t)HH * 192];            // enc W_ih, per-unit [r(64)|z(64)|n(64)]
__device__ float g_Wih_d[N3];                           // dec W_ih (scalar input), permuted

// ---------------- small PTX helpers ----------------
__device__ __forceinline__ void cp16(uint32_t smaddr, const void* g) {
    asm volatile("cp.async.cg.shared.global [%0], [%1], 16;" :: "r"(smaddr), "l"(g));
}
__device__ __forceinline__ void ldsm_x4(uint32_t* r, uint32_t addr) {
    asm volatile("ldmatrix.sync.aligned.m8n8.x4.shared.b16 {%0,%1,%2,%3}, [%4];"
                 : "=r"(r[0]), "=r"(r[1]), "=r"(r[2]), "=r"(r[3]) : "r"(addr));
}
__device__ __forceinline__ void ldsm_x2(uint32_t* r, uint32_t addr) {
    asm volatile("ldmatrix.sync.aligned.m8n8.x2.shared.b16 {%0,%1}, [%2];"
                 : "=r"(r[0]), "=r"(r[1]) : "r"(addr));
}
__device__ __forceinline__ void mma_bf16(float* c, const uint32_t* a, const uint32_t* b) {
    asm volatile("mma.sync.aligned.m16n8k16.row.col.f32.bf16.bf16.f32 "
                 "{%0,%1,%2,%3}, {%4,%5,%6,%7}, {%8,%9}, {%0,%1,%2,%3};"
                 : "+f"(c[0]), "+f"(c[1]), "+f"(c[2]), "+f"(c[3])
                 : "r"(a[0]), "r"(a[1]), "r"(a[2]), "r"(a[3]), "r"(b[0]), "r"(b[1]));
}

// ---------------- prep: build augmented, gate-interleaved bf16-split weights ----------------
// Permuted row j = 3u+g  <->  original row g*H+u.
// Augmented cols: k in [0,1024): W_hi[k]; [1024,2048): W_hi[k-1024]; [2048,3072): W_lo[k-2048]
__global__ void prep_weights(const float* __restrict__ encW, const float* __restrict__ decW) {
    size_t idx = (size_t)blockIdx.x * blockDim.x + threadIdx.x;
    const size_t one = (size_t)N3 * KK;
    if (idx >= 2 * one) return;
    int which = idx >= one;
    size_t rem = which ? idx - one : idx;
    int j = (int)(rem / KK);
    int k = (int)(rem % KK);
    int u = j / 3, g = j - 3 * u;
    int korig = k & 1023;
    int region = k >> 10;
    const float* W = which ? decW : encW;
    float w = W[(size_t)(g * HH + u) * HH + korig];
    __nv_bfloat16 hi = __float2bfloat16(w);
    __nv_bfloat16 out = (region < 2) ? hi : __float2bfloat16(w - __bfloat162float(hi));
    (which ? g_Waug_dec : g_Waug_enc)[(size_t)j * KK + k] = out;
}

// ---------------- prep: biases, permuted W_ih, zero h, init d_out = fc_b ----------------
__global__ void prep_misc(const float* __restrict__ ebih, const float* __restrict__ ebhh,
                          const float* __restrict__ dbih, const float* __restrict__ dbhh,
                          const float* __restrict__ eWih, const float* __restrict__ dWih,
                          const float* __restrict__ fcb, float* __restrict__ dout) {
    int tid = blockIdx.x * blockDim.x + threadIdx.x;
    int stride = gridDim.x * blockDim.x;
    for (int i = tid; i < N3; i += stride) {
        int u = i / 3, g = i - 3 * u;
        int o = g * HH + u;
        g_bih_e[i] = ebih[o];
        g_bhh_e[i] = ebhh[o];
        g_bih_d[i] = dbih[o];
        g_bhh_d[i] = dbhh[o];
        g_Wih_d[i] = dWih[o];    // dec_W_ih is [3H,1]
    }
    for (int i = tid; i < HH * 192; i += stride) {
        int u = i / 192, rem = i - u * 192;
        int g = rem >> 6, f = rem & 63;
        g_Wihp_e[i] = eWih[(size_t)(g * HH + u) * FF + f];
    }
    for (int i = tid; i < 2 * BB * KK / 2; i += stride) {   // zero both h buffers (as u32)
        ((uint32_t*)g_haug)[i] = 0u;
    }
    for (int i = tid; i < BB * TLEN; i += stride) dout[i] = fcb[0];
}

// ---------------- one recurrent step: GEMM (bf16x3) + fused GRU epilogue ----------------
// grid (32, 4): blockIdx.x = 96-col tile over N3, blockIdx.y = 64-row tile over batch.
// mode 0 = encoder (t indexes x), mode 1 = decoder (t = s; input is dout[:, s-1])
__global__ __launch_bounds__(256) void gru_step_kernel(
    int t, int mode, int par,
    const float* __restrict__ x, const float* __restrict__ fcW, float* __restrict__ dout)
{
    const __nv_bfloat16* __restrict__ Waug = mode ? g_Waug_dec : g_Waug_enc;
    const __nv_bfloat16* __restrict__ hsrc = g_haug[par];
    __nv_bfloat16* __restrict__ hdst = g_haug[par ^ 1];
    const float* __restrict__ bih = mode ? g_bih_d : g_bih_e;
    const float* __restrict__ bhh = mode ? g_bhh_d : g_bhh_e;

    extern __shared__ __align__(16) unsigned char smem_raw[];
    const int tid = threadIdx.x;
    const int lane = tid & 31, warp = tid >> 5;
    const int wm = warp >> 2, wn = warp & 3;     // 2 x 4 warps -> 32x24 warp tiles
    const int nb = blockIdx.x, mb = blockIdx.y;

    const uint32_t smBase = (uint32_t)__cvta_generic_to_shared(smem_raw);

    const __nv_bfloat16* Ag = hsrc + (size_t)(mb * 64) * KK;
    const __nv_bfloat16* Bg = Waug + (size_t)(nb * 96) * KK;

    // per-thread fixed load coordinates
    const int ra0 = tid >> 3, rs0 = tid & 7;        // A: 2 rounds cover 64 rows x 8 seg
    // issue loads of chunk `c` into stage slot `s`
    auto issue_chunk = [&](int c, int s) {
        const uint32_t sA = smBase + s * STAGE_BYTES;
        const uint32_t sB = sA + A_STAGE_BYTES;
        const int k0 = c * 64;
        #pragma unroll
        for (int q = 0; q < 2; q++) {
            int r = ra0 + q * 32;
            cp16(sA + r * 144 + rs0 * 16, Ag + (size_t)r * KK + k0 + rs0 * 8);
        }
        #pragma unroll
        for (int q = 0; q < 3; q++) {
            int r = ra0 + q * 32;
            cp16(sB + r * 144 + rs0 * 16, Bg + (size_t)r * KK + k0 + rs0 * 8);
        }
    };

    // ---- prologue: fill NSTG-1 stages ----
    #pragma unroll
    for (int s = 0; s < NSTG - 1; s++) {
        issue_chunk(s, s);
        asm volatile("cp.async.commit_group;" ::: "memory");
    }

    float acc[2][3][4];
    #pragma unroll
    for (int mi = 0; mi < 2; mi++)
        #pragma unroll
        for (int ni = 0; ni < 3; ni++)
            #pragma unroll
            for (int q = 0; q < 4; q++) acc[mi][ni][q] = 0.f;

    // ---- main K loop: NSTG-stage ring, one barrier per chunk ----
    for (int c = 0; c < NC; c++) {
        asm volatile("cp.async.wait_group %0;" :: "n"(NSTG - 2) : "memory");
        __syncthreads();
        // prefetch chunk c+NSTG-1 into the slot freed by chunk c-1
        {
            int cn = c + NSTG - 1;
            if (cn < NC) issue_chunk(cn, cn & (NSTG - 1));
            asm volatile("cp.async.commit_group;" ::: "memory");  // always commit (keeps group accounting uniform)
        }
        const int stg = c & (NSTG - 1);
        const uint32_t sA = smBase + stg * STAGE_BYTES;
        const uint32_t sB = sA + A_STAGE_BYTES;
        #pragma unroll
        for (int ks = 0; ks < 4; ks++) {
            uint32_t ra[2][4], rb[3][2];
            #pragma unroll
            for (int mi = 0; mi < 2; mi++) {
                int row = wm * 32 + mi * 16 + (lane & 15);
                int col = ks * 16 + (lane >> 4) * 8;
                ldsm_x4(ra[mi], sA + row * 144 + col * 2);
            }
            #pragma unroll
            for (int ni = 0; ni < 3; ni++) {
                int row = wn * 24 + ni * 8 + (lane & 7);
                int col = ks * 16 + ((lane >> 3) & 1) * 8;
                ldsm_x2(rb[ni], sB + row * 144 + col * 2);
            }
            #pragma unroll
            for (int mi = 0; mi < 2; mi++)
                #pragma unroll
                for (int ni = 0; ni < 3; ni++)
                    mma_bf16(acc[mi][ni], ra[mi], rb[ni]);
        }
    }

    // ---- stage accumulators to smem (reuse the pipeline buffers) ----
    __syncthreads();
    float* Csm = (float*)smem_raw;               // 64 x 96, pitch 99 floats (25344 B)
    float* Xs  = (float*)(smem_raw + 25600);     // 64 x 64 floats for x tile (16384 B)
    #pragma unroll
    for (int mi = 0; mi < 2; mi++)
        #pragma unroll
        for (int ni = 0; ni < 3; ni++) {
            int m = wm * 32 + mi * 16 + (lane >> 2);
            int n = wn * 24 + ni * 8 + ((lane & 3) << 1);
            Csm[m * 99 + n]           = acc[mi][ni][0];
            Csm[m * 99 + n + 1]       = acc[mi][ni][1];
            Csm[(m + 8) * 99 + n]     = acc[mi][ni][2];
            Csm[(m + 8) * 99 + n + 1] = acc[mi][ni][3];
        }
    if (mode == 0) {
        // cooperative load of this tile's x rows: 64 rows x 16 float4
        #pragma unroll
        for (int q = 0; q < 4; q++) {
            int id = tid + q * 256;
            int r = id >> 4, c4 = id & 15;
            ((float4*)Xs)[r * 16 + c4] =
                *(const float4*)(x + ((size_t)(mb * 64 + r) * TT + t) * FF + c4 * 4);
        }
    }
    __syncthreads();

    // ---- fused GRU epilogue: each thread owns (batch bl, 8 hidden units) ----
    const int bl = tid >> 2, uq = tid & 3;
    const int b = mb * 64 + bl;
    float inp = 0.f;
    if (mode && t > 0) inp = dout[b * TLEN + (t - 1)];
    float fcsum = 0.f;
    const float4* xs4 = (const float4*)(Xs + bl * 64);

    #pragma unroll
    for (int i = 0; i < 8; i++) {
        int ul = uq * 8 + i;
        int u = nb * 32 + ul;
        float ar = Csm[bl * 99 + ul * 3 + 0];
        float az = Csm[bl * 99 + ul * 3 + 1];
        float an = Csm[bl * 99 + ul * 3 + 2];
        float gr, gz, gn;
        if (mode == 0) {
            gr = gz = gn = 0.f;
            const float4* wr4 = (const float4*)(g_Wihp_e + (size_t)u * 192);
            #pragma unroll
            for (int q = 0; q < 16; q++) {
                float4 xv = xs4[q];
                float4 a = wr4[q], bq = wr4[16 + q], cq = wr4[32 + q];
                gr += xv.x * a.x + xv.y * a.y + xv.z * a.z + xv.w * a.w;
                gz += xv.x * bq.x + xv.y * bq.y + xv.z * bq.z + xv.w * bq.w;
                gn += xv.x * cq.x + xv.y * cq.y + xv.z * cq.z + xv.w * cq.w;
            }
        } else {
            gr = inp * g_Wih_d[u * 3 + 0];
            gz = inp * g_Wih_d[u * 3 + 1];
            gn = inp * g_Wih_d[u * 3 + 2];
        }
        float hprev = __bfloat162float(hsrc[(size_t)b * KK + u]) +
                      __bfloat162float(hsrc[(size_t)b * KK + 1024 + u]);
        float rg = 1.f / (1.f + __expf(-(gr + bih[u * 3 + 0] + ar + bhh[u * 3 + 0])));
        float zg = 1.f / (1.f + __expf(-(gz + bih[u * 3 + 1] + az + bhh[u * 3 + 1])));
        float ng = tanhf(gn + bih[u * 3 + 2] + rg * (an + bhh[u * 3 + 2]));
        float hn = (1.f - zg) * ng + zg * hprev;
        __nv_bfloat16 hi = __float2bfloat16(hn);
        hdst[(size_t)b * KK + u]        = hi;
        hdst[(size_t)b * KK + 2048 + u] = hi;
        hdst[(size_t)b * KK + 1024 + u] = __float2bfloat16(hn - __bfloat162float(hi));
        if (mode) fcsum += hn * fcW[u];
    }
    if (mode) {
        fcsum += __shfl_down_sync(0xffffffffu, fcsum, 2, 4);
        fcsum += __shfl_down_sync(0xffffffffu, fcsum, 1, 4);
        if (uq == 0) atomicAdd(&dout[b * TLEN + t], fcsum);
    }
}

// ---------------- host launch ----------------
extern "C" void kernel_launch(void* const* d_in, const int* in_sizes, int n_in,
                              void* d_out, int out_size) {
    const float* x    = (const float*)d_in[0];
    const float* eWih = (const float*)d_in[1];
    const float* eWhh = (const float*)d_in[2];
    const float* ebih = (const float*)d_in[3];
    const float* ebhh = (const float*)d_in[4];
    const float* dWih = (const float*)d_in[5];
    const float* dWhh = (const float*)d_in[6];
    const float* dbih = (const float*)d_in[7];
    const float* dbhh = (const float*)d_in[8];
    const float* fcW  = (const float*)d_in[9];
    const float* fcb  = (const float*)d_in[10];
    float* out = (float*)d_out;

    cudaFuncSetAttribute(gru_step_kernel,
                         cudaFuncAttributeMaxDynamicSharedMemorySize, SMEM_TOTAL);

    prep_weights<<<(2 * (size_t)N3 * KK + 255) / 256, 256>>>(eWhh, dWhh);
    prep_misc<<<1024, 256>>>(ebih, ebhh, dbih, dbhh, eWih, dWih, fcb, out);

    dim3 grid(N3 / 96, BB / 64);   // (32, 4)
    for (int t = 0; t < TT; t++)
        gru_step_kernel<<<grid, 256, SMEM_TOTAL>>>(t, 0, t & 1, x, fcW, out);
    for (int s = 0; s < TLEN; s++)
        gru_step_kernel<<<grid, 256, SMEM_TOTAL>>>(s, 1, s & 1, x, fcW, out);
}